// round 4
// baseline (speedup 1.0000x reference)
#include <cuda_runtime.h>

// Problem constants (fixed by the dataset)
#define BATCH   2048
#define LATD    32
#define HID     256
#define DIM     20
#define TSTEPS  512

#define ROWS    16                 // batch rows per CTA
#define RPT     8                  // rows per thread (2 halves)
#define RP      18                 // padded SMEM row stride (even: 8B-aligned ull loads)
#define NCTA    (BATCH / ROWS)     // 128 CTAs
#define NT      512                // 2 halves x 256 units

typedef unsigned long long ull;

// ---------------- packed weight scratch (repacked once per launch) ----------------
// Layout: A[k][unit][gate], gate fastest (float4 per (k,unit)).
__device__ float g_A0x[DIM * 4 * HID];
__device__ float g_A0h[HID * 4 * HID];
__device__ float g_A1x[HID * 4 * HID];
__device__ float g_A1h[HID * 4 * HID];
__device__ float g_PT [HID * DIM];         // w_proj^T: PT[k][d]

// ---------------- packed fp32x2 helpers ----------------
__device__ __forceinline__ ull dup2(float w) {
    ull d; asm("mov.b64 %0, {%1, %1};" : "=l"(d) : "f"(w)); return d;
}
__device__ __forceinline__ ull fma2(ull a, ull b, ull c) {
    ull d; asm("fma.rn.f32x2 %0, %1, %2, %3;" : "=l"(d) : "l"(a), "l"(b), "l"(c)); return d;
}
__device__ __forceinline__ float2 unpack2(ull v) {
    float2 f; asm("mov.b64 {%0, %1}, %2;" : "=f"(f.x), "=f"(f.y) : "l"(v)); return f;
}
__device__ __forceinline__ ull pack2(float a, float b) {
    ull d; asm("mov.b64 %0, {%1, %2};" : "=l"(d) : "f"(a), "f"(b)); return d;
}

// ---------------- saturation-safe fast transcendentals ----------------
__device__ __forceinline__ float sigm(float x) {
    return __fdividef(1.f, 1.f + __expf(-x));
}
__device__ __forceinline__ float tanh_(float x) {
    float e = __expf(2.f * x);
    return 1.f - __fdividef(2.f, e + 1.f);
}

// ---------------- weight repack kernel ----------------
__global__ void repack_kernel(const float* __restrict__ w_ih0,
                              const float* __restrict__ w_hh0,
                              const float* __restrict__ w_ih1,
                              const float* __restrict__ w_hh1,
                              const float* __restrict__ w_proj) {
    const int stride = gridDim.x * blockDim.x;
    const int base   = blockIdx.x * blockDim.x + threadIdx.x;
    for (int idx = base; idx < DIM * HID * 4; idx += stride) {
        int k = idx / (HID * 4), ug = idx % (HID * 4), u = ug >> 2, g = ug & 3;
        g_A0x[idx] = w_ih0[(g * HID + u) * DIM + k];
    }
    for (int idx = base; idx < HID * HID * 4; idx += stride) {
        int k = idx / (HID * 4), ug = idx % (HID * 4), u = ug >> 2, g = ug & 3;
        int src = (g * HID + u) * HID + k;
        g_A0h[idx] = w_hh0[src];
        g_A1x[idx] = w_ih1[src];
        g_A1h[idx] = w_hh1[src];
    }
    for (int idx = base; idx < HID * DIM; idx += stride) {
        int k = idx / DIM, d = idx % DIM;
        g_PT[idx] = w_proj[d * HID + k];
    }
}

// ---------------- gate GEMM: acc[g][rp] += A[k][unit][g] * hs[k][rb+2rp .. rb+2rp+1] ----------------
template <int K>
__device__ __forceinline__ void gemm_packed(const float* __restrict__ wp,
                                            const float* __restrict__ hs,
                                            int unit, int rb, ull (&acc)[4][4]) {
    const float4* wv = reinterpret_cast<const float4*>(wp) + unit;
    #pragma unroll 4
    for (int k = 0; k < K; ++k) {
        float4 w4 = __ldg(wv + (size_t)k * HID);     // coalesced LDG.128 per warp
        const float* hp = hs + k * RP + rb;
        ull h2[4];
        #pragma unroll
        for (int rp = 0; rp < 4; ++rp)
            h2[rp] = *reinterpret_cast<const ull*>(hp + 2 * rp);
        ull w0 = dup2(w4.x), w1 = dup2(w4.y), w2 = dup2(w4.z), w3 = dup2(w4.w);
        #pragma unroll
        for (int rp = 0; rp < 4; ++rp) {
            acc[0][rp] = fma2(h2[rp], w0, acc[0][rp]);
            acc[1][rp] = fma2(h2[rp], w1, acc[1][rp]);
            acc[2][rp] = fma2(h2[rp], w2, acc[2][rp]);
            acc[3][rp] = fma2(h2[rp], w3, acc[3][rp]);
        }
    }
}

__device__ __forceinline__ void cell_update(ull (&acc)[4][4],
                                            float (&c)[RPT], float (&hnew)[RPT]) {
    #pragma unroll
    for (int rp = 0; rp < 4; ++rp) {
        float2 gi = unpack2(acc[0][rp]);
        float2 gf = unpack2(acc[1][rp]);
        float2 gg = unpack2(acc[2][rp]);
        float2 go = unpack2(acc[3][rp]);
        {
            int r = 2 * rp;
            float cc = sigm(gf.x) * c[r] + sigm(gi.x) * tanh_(gg.x);
            c[r] = cc;  hnew[r] = sigm(go.x) * tanh_(cc);
        }
        {
            int r = 2 * rp + 1;
            float cc = sigm(gf.y) * c[r] + sigm(gi.y) * tanh_(gg.y);
            c[r] = cc;  hnew[r] = sigm(go.y) * tanh_(cc);
        }
    }
}

__global__ void __launch_bounds__(NT, 1)
decoder_kernel(const float* __restrict__ z,
               const float* __restrict__ w_lh, const float* __restrict__ b_lh,
               const float* __restrict__ w_lc, const float* __restrict__ b_lc,
               const float* __restrict__ b_ih0, const float* __restrict__ b_hh0,
               const float* __restrict__ b_ih1, const float* __restrict__ b_hh1,
               const float* __restrict__ b_proj,
               float* __restrict__ out) {
    __shared__ __align__(16) float h0_s[HID * RP];
    __shared__ __align__(16) float h1_s[HID * RP];
    __shared__ __align__(16) float x_s[DIM * RP];
    __shared__ __align__(16) float z_s[ROWS * LATD];

    const int tid  = threadIdx.x;
    const int unit = tid & (HID - 1);     // 0..255
    const int half = tid >> 8;            // 0..1
    const int rb   = half * RPT;          // row base within CTA slab
    const int r0   = blockIdx.x * ROWS;

    // ---- load z slab, zero x0 ----
    z_s[tid] = z[(size_t)(r0 + tid / LATD) * LATD + (tid % LATD)];
    for (int i = tid; i < DIM * RP; i += NT) x_s[i] = 0.f;
    __syncthreads();

    // ---- init h/c : h_init = z @ w_lh^T + b_lh ; reshape(B,2,H) ----
    float c0r[RPT], c1r[RPT];
    {
        float h0v[RPT], h1v[RPT];
        #pragma unroll
        for (int r = 0; r < RPT; ++r) {
            h0v[r] = b_lh[unit];  h1v[r] = b_lh[HID + unit];
            c0r[r] = b_lc[unit];  c1r[r] = b_lc[HID + unit];
        }
        const float* wl0 = w_lh + (size_t)unit * LATD;
        const float* wl1 = w_lh + (size_t)(HID + unit) * LATD;
        const float* wc0 = w_lc + (size_t)unit * LATD;
        const float* wc1 = w_lc + (size_t)(HID + unit) * LATD;
        for (int k = 0; k < LATD; ++k) {
            float a0 = wl0[k], a1 = wl1[k], a2 = wc0[k], a3 = wc1[k];
            #pragma unroll
            for (int r = 0; r < RPT; ++r) {
                float zv = z_s[(rb + r) * LATD + k];
                h0v[r] = fmaf(zv, a0, h0v[r]);
                h1v[r] = fmaf(zv, a1, h1v[r]);
                c0r[r] = fmaf(zv, a2, c0r[r]);
                c1r[r] = fmaf(zv, a3, c1r[r]);
            }
        }
        #pragma unroll
        for (int r = 0; r < RPT; ++r) {
            h0_s[unit * RP + rb + r] = h0v[r];
            h1_s[unit * RP + rb + r] = h1v[r];
        }
    }

    // ---- fused gate biases ----
    float bias0[4], bias1[4];
    #pragma unroll
    for (int g = 0; g < 4; ++g) {
        bias0[g] = b_ih0[g * HID + unit] + b_hh0[g * HID + unit];
        bias1[g] = b_ih1[g * HID + unit] + b_hh1[g * HID + unit];
    }

    // ---- projection mapping: 320 threads, one (row, dim) each ----
    const int pr = tid / DIM;             // 0..15 for tid<320
    const int pd = tid - pr * DIM;        // 0..19
    const bool do_proj = (tid < ROWS * DIM);
    const float pbias = do_proj ? b_proj[pd] : 0.f;

    __syncthreads();

    // =============================== time loop ===============================
    for (int t = 0; t < TSTEPS; ++t) {
        ull acc[4][4];
        float hnew[RPT];

        // ---- layer 0 ----
        #pragma unroll
        for (int g = 0; g < 4; ++g) {
            ull bd = dup2(bias0[g]);
            #pragma unroll
            for (int rp = 0; rp < 4; ++rp) acc[g][rp] = bd;
        }
        gemm_packed<DIM>(g_A0x, x_s, unit, rb, acc);
        gemm_packed<HID>(g_A0h, h0_s, unit, rb, acc);
        cell_update(acc, c0r, hnew);
        __syncthreads();                       // readers of old h0 done
        #pragma unroll
        for (int rp = 0; rp < 4; ++rp)
            *reinterpret_cast<ull*>(h0_s + unit * RP + rb + 2 * rp) =
                pack2(hnew[2 * rp], hnew[2 * rp + 1]);
        __syncthreads();                       // new h0 visible

        // ---- layer 1 ----
        #pragma unroll
        for (int g = 0; g < 4; ++g) {
            ull bd = dup2(bias1[g]);
            #pragma unroll
            for (int rp = 0; rp < 4; ++rp) acc[g][rp] = bd;
        }
        gemm_packed<HID>(g_A1x, h0_s, unit, rb, acc);
        gemm_packed<HID>(g_A1h, h1_s, unit, rb, acc);
        cell_update(acc, c1r, hnew);
        __syncthreads();                       // readers of old h1 done
        #pragma unroll
        for (int rp = 0; rp < 4; ++rp)
            *reinterpret_cast<ull*>(h1_s + unit * RP + rb + 2 * rp) =
                pack2(hnew[2 * rp], hnew[2 * rp + 1]);
        __syncthreads();                       // new h1 visible

        // ---- projection: y = h1 @ w_proj^T + b_proj ; feed back ----
        if (do_proj) {
            float pa = pbias;
            #pragma unroll 8
            for (int k = 0; k < HID; ++k) {
                float wv = __ldg(g_PT + k * DIM + pd);
                pa = fmaf(h1_s[k * RP + pr], wv, pa);
            }
            out[(size_t)(r0 + pr) * TSTEPS * DIM + (size_t)t * DIM + pd] = pa;
            x_s[pd * RP + pr] = pa;
        }
        __syncthreads();                       // next x visible for t+1
    }
}

extern "C" void kernel_launch(void* const* d_in, const int* in_sizes, int n_in,
                              void* d_out, int out_size) {
    const int wbase = (n_in >= 17) ? 3 : 2;

    const float* z      = (const float*)d_in[0];
    const float* w_lh   = (const float*)d_in[wbase + 0];
    const float* b_lh   = (const float*)d_in[wbase + 1];
    const float* w_lc   = (const float*)d_in[wbase + 2];
    const float* b_lc   = (const float*)d_in[wbase + 3];
    const float* w_ih0  = (const float*)d_in[wbase + 4];
    const float* w_hh0  = (const float*)d_in[wbase + 5];
    const float* b_ih0  = (const float*)d_in[wbase + 6];
    const float* b_hh0  = (const float*)d_in[wbase + 7];
    const float* w_ih1  = (const float*)d_in[wbase + 8];
    const float* w_hh1  = (const float*)d_in[wbase + 9];
    const float* b_ih1  = (const float*)d_in[wbase + 10];
    const float* b_hh1  = (const float*)d_in[wbase + 11];
    const float* w_proj = (const float*)d_in[wbase + 12];
    const float* b_proj = (const float*)d_in[wbase + 13];

    repack_kernel<<<256, 256>>>(w_ih0, w_hh0, w_ih1, w_hh1, w_proj);
    decoder_kernel<<<NCTA, NT>>>(z, w_lh, b_lh, w_lc, b_lc,
                                 b_ih0, b_hh0, b_ih1, b_hh1,
                                 b_proj, (float*)d_out);
}